// round 17
// baseline (speedup 1.0000x reference)
#include <cuda_runtime.h>
#include <cuda_fp16.h>
#include <cstdint>

// ===================== problem constants =====================
// x: 262144 rows x 128; W: (8,128,128); b: (8,128)
// CTA: one (b,i) block = 256 rows, processed as 2 sequential 128-row jobs.
// Single kernel: W fp16 fragment image built in-CTA (coalesced) from raw W.
#define N_DIM      128
#define K_DIM      128
#define THREADS    256
#define NUM_CTAS   1024
#define K_CHUNK    32
#define NCHUNK     4

// ---- smem layout (32-bit words) ----
// [W fp16 frag image: 8192 words][A fp16 2 bufs: 2x2560 words][bias 128]
#define OFF_W       0
#define W_IMG_WORDS 8192
#define F16_STRIDE_H 40                       // halves per A row -> LDSM conflict-free
#define F16_BUF_WORDS (128 * 20)              // 2560 words = 10KB per parity buf
#define OFF_A       W_IMG_WORDS               // 8192
#define OFF_BIAS    (OFF_A + 2 * F16_BUF_WORDS)   // 13312
#define SMEM_FLOATS (OFF_BIAS + 128)
#define SMEM_BYTES  (SMEM_FLOATS * 4)         // 53,760 (x2 CTAs = 107.5KB)

// ===================== helpers =====================
__device__ __forceinline__ uint32_t smem_u32(const void* p) {
    uint32_t a;
    asm("{ .reg .u64 t; cvta.to.shared.u64 t, %1; cvt.u32.u64 %0, t; }" : "=r"(a) : "l"(p));
    return a;
}
__device__ __forceinline__ void ldsm_x4(uint32_t& r0, uint32_t& r1, uint32_t& r2, uint32_t& r3,
                                        uint32_t addr) {
    asm volatile("ldmatrix.sync.aligned.m8n8.x4.shared.b16 {%0,%1,%2,%3}, [%4];"
                 : "=r"(r0), "=r"(r1), "=r"(r2), "=r"(r3) : "r"(addr));
}
// m16n8k16 fp16 MMA, fp32 accumulate
__device__ __forceinline__ void mma_f16(float* c, const uint32_t* a, uint32_t b0, uint32_t b1) {
    asm volatile(
        "mma.sync.aligned.m16n8k16.row.col.f32.f16.f16.f32 "
        "{%0,%1,%2,%3}, {%4,%5,%6,%7}, {%8,%9}, {%0,%1,%2,%3};"
        : "+f"(c[0]), "+f"(c[1]), "+f"(c[2]), "+f"(c[3])
        : "r"(a[0]), "r"(a[1]), "r"(a[2]), "r"(a[3]), "r"(b0), "r"(b1));
}

// ===================== main GEMM (single kernel, 2 jobs/CTA) =====================
// W fp16 fragment image layout (validated rounds 8-16), now ks-swizzled:
//   fragment float4 for (p_global, ks) lives at f4 index
//     kc*512 + (p_global*2+ks)*32 + (lane ^ (ks*4))
//   holding { b0(nt=2p), b1(nt=2p), b0(nt=2p+1), b1(nt=2p+1) } fp16x2.
__global__ __launch_bounds__(THREADS, 2)
void gemm_kernel(const float* __restrict__ x, const float* __restrict__ Wraw,
                 const float* __restrict__ bias, float* __restrict__ out) {
    extern __shared__ __align__(16) float smem[];
    const uint32_t sm_base = smem_u32(smem);

    const int tid  = threadIdx.x;
    const int lane = tid & 31;
    const int wid  = tid >> 5;
    const int blk  = blockIdx.x;
    const int ch   = blk & 7;             // (b,i) block index -> channel i

    const float* a_base = x + (size_t)blk * (256 * K_DIM);
    float*       o_base = out + (size_t)blk * (256 * N_DIM);

    // per-thread A piece coordinates: rows arow+{0,32,64,96}, 4-col group apc
    const int arow = tid >> 3;
    const int apc  = tid & 7;

    // ---- prologue A: issue job-0 chunk-0 LDGs first (DRAM latency cover) ----
    float4 v[4];
#pragma unroll
    for (int i = 0; i < 4; i++)
        v[i] = *(const float4*)(a_base + (size_t)(arow + i * 32) * K_DIM + apc * 4);
    float bval = (tid < 128) ? bias[ch * 128 + tid] : 0.0f;

    // ---- prologue B: build W fp16 fragment image (coalesced LDG.64, swizzled STS) ----
    {
        const float* Wch = Wraw + ch * (N_DIM * K_DIM);
        uint32_t* const wimg = (uint32_t*)smem + OFF_W;
#pragma unroll 4
        for (int it = 0; it < 32; it++) {
            int gw = it * THREADS + tid;      // 0..8191 image words
            int n  = gw >> 6;                 // output feature
            int kw = gw & 63;                 // k word (k = 2*kw)
            float2 wv = *(const float2*)(Wch + n * K_DIM + kw * 2);
            __half2 h2 = __float22half2_rn(wv);
            int kc  = kw >> 4;
            int ks  = (kw >> 3) & 1;
            int bix = (kw >> 2) & 1;
            int lane0 = ((n & 7) << 2) | (kw & 3);
            int p = n >> 4;
            int e = ((n >> 3) & 1) * 2 + bix;
            int fi4 = (((p * 2 + ks) * 32 + lane0) ^ (ks << 2));
            wimg[kc * 2048 + fi4 * 4 + e] = *(uint32_t*)&h2;
        }
    }
    if (tid < 128) smem[OFF_BIAS + tid] = bval;

    // 8 warps: 4 over M (32 rows each), 2 over N (64 cols each)
    const int warpM = (wid >> 1) * 32;
    const int h     = (wid & 1);

    uint32_t* const abufw = (uint32_t*)(smem + OFF_A);   // word view of fp16 A bufs

    // LDSM per-lane base (halves): row = warpM + (lane&7) + ((lane>>3)&1)*8, +8 halves lanes 16-31
    const uint32_t a_lane_h =
        (uint32_t)((warpM + (lane & 7) + ((lane >> 3) & 1) * 8) * F16_STRIDE_H
                   + (lane >> 4) * 8);
    const uint32_t f16_base = sm_base + OFF_A * 4u;
    // reader f4 offsets: ks=0 uses +lane, ks=1 uses +(lane^4)
    const int bo0 = h * 256 + lane;
    const int bo1 = h * 256 + (lane ^ 4);

#pragma unroll
    for (int jb = 0; jb < 2; jb++) {
        const float* a_b = a_base + (size_t)jb * (128 * K_DIM);
        float*       o_b = o_base + (size_t)jb * (128 * N_DIM);

        // STS chunk 0 of this job -> buf 0  (jb=0: v from prologue; jb=1: loaded in jb0 kc3)
#pragma unroll
        for (int i = 0; i < 4; i++) {
            __half2 h0 = __float22half2_rn(make_float2(v[i].x, v[i].y));
            __half2 h1 = __float22half2_rn(make_float2(v[i].z, v[i].w));
            uint2 pk; pk.x = *(uint32_t*)&h0; pk.y = *(uint32_t*)&h1;
            *(uint2*)(abufw + (arow + i * 32) * 20 + apc * 2) = pk;
        }
        __syncthreads();                  // jb=0: also publishes W image + bias

        float acc[2][8][4];
#pragma unroll
        for (int mt = 0; mt < 2; mt++)
#pragma unroll
            for (int nt = 0; nt < 8; nt++)
#pragma unroll
                for (int q = 0; q < 4; q++) acc[mt][nt][q] = 0.0f;

#pragma unroll
        for (int kc = 0; kc < NCHUNK; kc++) {
            const int par = kc & 1;

            // LDG next chunk (or next job's chunk 0) — covered by the MMA block below
            if (kc < NCHUNK - 1) {
#pragma unroll
                for (int i = 0; i < 4; i++)
                    v[i] = *(const float4*)(a_b + (size_t)(arow + i * 32) * K_DIM
                                            + (kc + 1) * K_CHUNK + apc * 4);
            } else if (jb == 0) {
#pragma unroll
                for (int i = 0; i < 4; i++)
                    v[i] = *(const float4*)(a_base + (size_t)(128 + arow + i * 32) * K_DIM
                                            + apc * 4);
            }

            // ---- MMA phase on buf[par], W frags for this kc ----
            const float4* bWc = (const float4*)(smem + OFF_W) + kc * 512;
            const uint32_t aL = f16_base + (uint32_t)(par * F16_BUF_WORDS) * 4u + a_lane_h * 2u;

            uint32_t afr[2][2][4];
#pragma unroll
            for (int mt = 0; mt < 2; mt++)
                ldsm_x4(afr[0][mt][0], afr[0][mt][1], afr[0][mt][2], afr[0][mt][3],
                        aL + (uint32_t)(mt * 16 * F16_STRIDE_H * 2));

#pragma unroll
            for (int ks = 0; ks < 2; ks++) {
                const float4* bW = bWc + (ks ? bo1 : bo0) + ks * 32;
                float4 f0 = bW[0 * 64];
                float4 f1 = bW[1 * 64];
                float4 f2 = bW[2 * 64];
                float4 f3 = bW[3 * 64];

                if (ks == 0) {
#pragma unroll
                    for (int mt = 0; mt < 2; mt++)
                        ldsm_x4(afr[1][mt][0], afr[1][mt][1], afr[1][mt][2], afr[1][mt][3],
                                aL + (uint32_t)((mt * 16 * F16_STRIDE_H + 16) * 2));
                }

                const float4 fr[4] = {f0, f1, f2, f3};
#pragma unroll
                for (int p = 0; p < 4; p++) {
                    uint32_t b0e = __float_as_uint(fr[p].x), b1e = __float_as_uint(fr[p].y);
                    uint32_t b0o = __float_as_uint(fr[p].z), b1o = __float_as_uint(fr[p].w);
                    mma_f16(acc[0][2 * p],     afr[ks][0], b0e, b1e);
                    mma_f16(acc[0][2 * p + 1], afr[ks][0], b0o, b1o);
                    mma_f16(acc[1][2 * p],     afr[ks][1], b0e, b1e);
                    mma_f16(acc[1][2 * p + 1], afr[ks][1], b0o, b1o);
                }
            }

            // ---- cvt + STS next chunk into opposite buffer; single barrier ----
            if (kc < NCHUNK - 1) {
                const int npar = par ^ 1;
#pragma unroll
                for (int i = 0; i < 4; i++) {
                    __half2 h0 = __float22half2_rn(make_float2(v[i].x, v[i].y));
                    __half2 h1 = __float22half2_rn(make_float2(v[i].z, v[i].w));
                    uint2 pk; pk.x = *(uint32_t*)&h0; pk.y = *(uint32_t*)&h1;
                    *(uint2*)(abufw + npar * F16_BUF_WORDS
                              + (arow + i * 32) * 20 + apc * 2) = pk;
                }
                __syncthreads();
            }
        }

        // ---- epilogue: accum + bias -> gmem (float2, full 32B sectors) ----
        const float* sB = smem + OFF_BIAS;
        const int r0 = warpM + (lane >> 2);
        const int n0 = h * 64 + (lane & 3) * 2;
#pragma unroll
        for (int mt = 0; mt < 2; mt++) {
#pragma unroll
            for (int hh = 0; hh < 2; hh++) {
                int row = r0 + mt * 16 + hh * 8;
                float* orow = o_b + (size_t)row * N_DIM;
#pragma unroll
                for (int nt = 0; nt < 8; nt++) {
                    int n = n0 + nt * 8;
                    float2 vv;
                    vv.x = acc[mt][nt][hh * 2 + 0] + sB[n];
                    vv.y = acc[mt][nt][hh * 2 + 1] + sB[n + 1];
                    *(float2*)(orow + n) = vv;
                }
            }
        }
    }
}

// ===================== launch (single kernel) =====================
extern "C" void kernel_launch(void* const* d_in, const int* in_sizes, int n_in,
                              void* d_out, int out_size) {
    const float* x = (const float*)d_in[0];
    const float* W = (const float*)d_in[1];
    const float* b = (const float*)d_in[2];
    float* out = (float*)d_out;

    cudaFuncSetAttribute(gemm_kernel, cudaFuncAttributeMaxDynamicSharedMemorySize, SMEM_BYTES);
    gemm_kernel<<<NUM_CTAS, THREADS, SMEM_BYTES>>>(x, W, b, out);
}